// round 16
// baseline (speedup 1.0000x reference)
#include <cuda_runtime.h>
#include <cuda_fp16.h>
#include <math.h>
#include <cstdint>

#define NN 3072
#define HEADS 4
#define IN_DIM 256
#define H1 128
#define H2 64
#define ADJW (NN/32)

typedef unsigned int u32;
typedef unsigned short u16;

// ---------------- scratch ----------------
__device__ __align__(16) unsigned g_adjbits[NN * ADJW];
__device__ __align__(16) float g_Whbuf[HEADS * NN * H1];
__device__ __align__(16) float g_src[HEADS * NN];
__device__ __align__(16) float g_dst[HEADS * NN];
__device__ __align__(16) float g_e1s[HEADS * NN];
__device__ __align__(16) float g_e2s[HEADS * NN];
__device__ __align__(16) float g_e1d[HEADS * NN];
__device__ __align__(16) float g_e2d[HEADS * NN];
__device__ unsigned g_maxenc[HEADS];
__device__ __align__(16) u16 g_WhH[HEADS * NN * H1];   // fp16 Wh, 128-row-tile-major + swizzled
__device__ __align__(16) float g_hcat[NN * HEADS * H1];
__device__ __align__(16) float g_h1[NN * H1];

// ---------------- helpers ----------------
__device__ __forceinline__ unsigned enc_f(float v) {
    int b = __float_as_int(v);
    return b >= 0 ? ((unsigned)b | 0x80000000u) : (unsigned)(~b);
}
__device__ __forceinline__ float dec_f(unsigned e) {
    return (e & 0x80000000u) ? __uint_as_float(e & 0x7fffffffu)
                             : __uint_as_float(~e);
}
__device__ __forceinline__ u32 smem_u32(const void* p) {
    u32 a;
    asm("{ .reg .u64 t; cvta.to.shared.u64 t, %1; cvt.u32.u64 %0, t; }" : "=r"(a) : "l"(p));
    return a;
}
__device__ __forceinline__ void ldsm4(u32* r, u32 addr) {
    asm volatile("ldmatrix.sync.aligned.m8n8.x4.shared.b16 {%0,%1,%2,%3}, [%4];"
                 : "=r"(r[0]), "=r"(r[1]), "=r"(r[2]), "=r"(r[3]) : "r"(addr));
}
__device__ __forceinline__ void ldsm4t(u32* r, u32 addr) {
    asm volatile("ldmatrix.sync.aligned.m8n8.x4.trans.shared.b16 {%0,%1,%2,%3}, [%4];"
                 : "=r"(r[0]), "=r"(r[1]), "=r"(r[2]), "=r"(r[3]) : "r"(addr));
}
__device__ __forceinline__ void mma_f16(float* d, const u32* a, const u32* b) {
    asm volatile(
        "mma.sync.aligned.m16n8k16.row.col.f32.f16.f16.f32 "
        "{%0,%1,%2,%3}, {%4,%5,%6,%7}, {%8,%9}, {%0,%1,%2,%3};"
        : "+f"(d[0]), "+f"(d[1]), "+f"(d[2]), "+f"(d[3])
        : "r"(a[0]), "r"(a[1]), "r"(a[2]), "r"(a[3]), "r"(b[0]), "r"(b[1]));
}
#define CP_ASYNC16(dst, src) asm volatile("cp.async.cg.shared.global [%0], [%1], 16;" :: "r"(dst), "l"(src))
#define CP_COMMIT()  asm volatile("cp.async.commit_group;" ::: "memory")
#define CP_WAIT0()   asm volatile("cp.async.wait_group 0;" ::: "memory")
#define MBAR_INIT(a, c) asm volatile("mbarrier.init.shared.b64 [%0], %1;" :: "r"(a), "r"(c) : "memory")
#define MBAR_EXPECT_TX(a, bytes) \
    asm volatile("mbarrier.arrive.expect_tx.shared.b64 _, [%0], %1;" :: "r"(a), "r"(bytes) : "memory")
__device__ __forceinline__ void mbar_wait(u32 mbar, u32 parity) {
    asm volatile(
        "{\n\t.reg .pred P1;\n\t"
        "WL%=:\n\t"
        "mbarrier.try_wait.parity.acquire.cta.shared::cta.b64 P1, [%0], %1, 0x989680;\n\t"
        "@P1 bra.uni WD%=;\n\t"
        "bra.uni WL%=;\n\t"
        "WD%=:\n\t}"
        :: "r"(mbar), "r"(parity) : "memory");
}
#define CP_BULK(dst, src, bytes, mbar) \
    asm volatile("cp.async.bulk.shared::cta.global.mbarrier::complete_tx::bytes [%0], [%1], %2, [%3];" \
                 :: "r"(dst), "l"(src), "r"(bytes), "r"(mbar) : "memory")

// ---------------- adjacency bit-pack (+ maxenc zero for layer 1) ----------------
__global__ void pack_adj_k(const int* __restrict__ adj) {
    int idx = blockIdx.x * blockDim.x + threadIdx.x;
    if (idx < HEADS) g_maxenc[idx] = 0u;
    int v = adj[idx] > 0;
    unsigned m = __ballot_sync(0xffffffffu, v);
    if ((idx & 31) == 0) g_adjbits[idx >> 5] = m;
}

// ---------------- per-head GEMM: Wh[h] = X @ W[h] (+ 128-row-tiled/swizzled fp16) ----------------
__global__ __launch_bounds__(256) void gemm_heads_k(
    const float* __restrict__ X, const float* __restrict__ W,
    float* __restrict__ out, u16* __restrict__ hi,
    int K, int F)
{
    int h = blockIdx.z;
    int m0 = blockIdx.x * 64, n0 = blockIdx.y * 64;
    const float* Wp = W + (size_t)h * K * F;
    size_t obase = (size_t)h * NN * F;
    char* hibase = (char*)hi + (size_t)h * NN * F * 2;
    __shared__ float Xs[64][17];
    __shared__ __align__(16) float Ws[16][64];
    int tid = threadIdx.x, ty = tid / 16, tx = tid % 16;
    float acc[4][4] = {};
    for (int kt = 0; kt < K; kt += 16) {
        int r = tid >> 2, c = (tid & 3) * 4;
        float4 xv = *(const float4*)&X[(size_t)(m0 + r) * K + kt + c];
        Xs[r][c] = xv.x; Xs[r][c + 1] = xv.y; Xs[r][c + 2] = xv.z; Xs[r][c + 3] = xv.w;
        int r2 = tid >> 4, c2 = (tid & 15) * 4;
        *(float4*)&Ws[r2][c2] = *(const float4*)&Wp[(size_t)(kt + r2) * F + n0 + c2];
        __syncthreads();
#pragma unroll
        for (int k = 0; k < 16; k++) {
            float a[4], b[4];
#pragma unroll
            for (int i = 0; i < 4; i++) a[i] = Xs[ty * 4 + i][k];
#pragma unroll
            for (int j = 0; j < 4; j++) b[j] = Ws[k][tx * 4 + j];
#pragma unroll
            for (int i = 0; i < 4; i++)
#pragma unroll
                for (int j = 0; j < 4; j++) acc[i][j] = fmaf(a[i], b[j], acc[i][j]);
        }
        __syncthreads();
    }
#pragma unroll
    for (int i = 0; i < 4; i++) {
        int n = m0 + ty * 4 + i;
        int f0 = n0 + tx * 4;
        size_t o = obase + (size_t)n * F + f0;
        *(float4*)&out[o] = make_float4(acc[i][0], acc[i][1], acc[i][2], acc[i][3]);
        __half2 h01 = __floats2half2_rn(acc[i][0], acc[i][1]);
        __half2 h23 = __floats2half2_rn(acc[i][2], acc[i][3]);
        uint2 pk;
        pk.x = *(u32*)&h01;
        pk.y = *(u32*)&h23;
        int t = n >> 7, r = n & 127;
        int c = f0 >> 3;
        size_t off = (size_t)t * (128 * F * 2) + (size_t)r * F * 2
                   + (size_t)((c ^ (r & 7)) << 4) + (f0 & 7) * 2;
        *(uint2*)(hibase + off) = pk;
    }
}

// ---------------- src/dst projections + per-head max(dst) ----------------
__global__ void srcdst_k(const float* __restrict__ Wh, const float* __restrict__ as,
                         const float* __restrict__ ad, int F)
{
    int w = (blockIdx.x * blockDim.x + threadIdx.x) >> 5;
    int lane = threadIdx.x & 31;
    if (w >= HEADS * NN) return;
    int h = w / NN;
    const float* row = Wh + (size_t)w * F;
    float ss = 0.f, dd = 0.f;
    for (int f = lane; f < F; f += 32) {
        float v = row[f];
        ss = fmaf(v, as[h * F + f], ss);
        dd = fmaf(v, ad[h * F + f], dd);
    }
#pragma unroll
    for (int o = 16; o; o >>= 1) {
        ss += __shfl_xor_sync(0xffffffffu, ss, o);
        dd += __shfl_xor_sync(0xffffffffu, dd, o);
    }
    if (!lane) {
        g_src[w] = ss; g_dst[w] = dd;
        atomicMax(&g_maxenc[h], enc_f(dd));
    }
}

// ---------------- factored exps ----------------
__global__ void exps_k() {
    int i = blockIdx.x * blockDim.x + threadIdx.x;
    if (i >= HEADS * NN) return;
    int h = i / NN;
    float s = g_src[i], d = g_dst[i];
    float x = s + dec_f(g_maxenc[h]);
    float c = x > 0.f ? x : 0.2f * x;
    g_e1s[i] = expf(s - c);
    g_e2s[i] = expf(0.2f * s - c);
    g_e1d[i] = expf(d);
    g_e2d[i] = expf(0.2f * d);
}

// ---------------- HMMA attention: D = P @ Wh (fp16, BM=64, BK=128, 2 CTA/SM) ----------------
// grid (NN/64, HEADS), block 256 (8 warps: 2 m-groups x 4 n-groups)
template <int F>
__global__ __launch_bounds__(256, 2) void attn_mma_k(
    const u16* __restrict__ WhH, float* __restrict__ hcat)
{
    constexpr int BM = 64;
    constexpr int BK = 128;
    constexpr int NIT = NN / BK;          // 24
    constexpr int PST = BK + 8;           // 136 halves
    constexpr int NW = F / 4;             // cols per n-group (32 / 16)
    constexpr int NT = NW / 8;            // 4 (F=128) / 2 (F=64)
    constexpr int NG = NT / 2;            // 2 / 1
    constexpr int SZ_P = BM * PST * 2;    // 17,408 B
    constexpr int SZ_B = BK * F * 2;
    constexpr int SZ_DJ = 3 * BK * 4;     // 1,536 B
    constexpr int OFF_P = 0;
    constexpr int OFF_B = 2 * SZ_P;
    constexpr int OFF_DJ = OFF_B + 2 * SZ_B;
    constexpr int OFF_RS = OFF_DJ + 2 * SZ_DJ;
    constexpr int OFF_MB = OFF_RS + 256;

    extern __shared__ char sm[];
    u32 smb = smem_u32(sm);
    float* rsum = (float*)(sm + OFF_RS);

    int tid = threadIdx.x, wid = tid >> 5, lane = tid & 31;
    int h = blockIdx.y, m0 = blockIdx.x * BM;
    int base = h * NN;
    const char* WHt = (const char*)WhH + (size_t)base * F * 2;

    // P-build role: 4 threads per row, 32 cols (one adj word) each
    int rr = tid >> 2, q = tid & 3, kb = q * 32;
    float E1s = g_e1s[base + m0 + rr];
    float E2s = g_e2s[base + m0 + rr];
    float srcv = g_src[base + m0 + rr];
    float psum = 0.f;
    u32 adjrow_base = (u32)((m0 + rr) * ADJW) + q;

    // mma role: 2 m-groups (32 rows) x 4 n-groups (F/4 cols)
    int wm = wid & 1, wn = wid >> 1;
    int mrow0 = wm * 32, nb0 = wn * NW;
    float acc[2][NT][4];
#pragma unroll
    for (int i = 0; i < 2; i++)
#pragma unroll
        for (int j = 0; j < NT; j++)
#pragma unroll
            for (int p = 0; p < 4; p++) acc[i][j][p] = 0.f;

    u32 aoff = (u32)(((mrow0 + (lane & 15)) * PST + (lane >> 4) * 8) * 2);

    auto stage = [&](int s, int kt) {
        if (tid == 0) {
            u32 mb = smb + OFF_MB + s * 8;
            MBAR_EXPECT_TX(mb, (u32)SZ_B);
            CP_BULK(smb + OFF_B + s * SZ_B, WHt + (size_t)(kt / BK) * SZ_B, (u32)SZ_B, mb);
        }
        if (tid < 96) {
            int which = tid >> 5, qq = tid & 31;
            const float* src = (which == 0 ? g_dst : which == 1 ? g_e1d : g_e2d)
                               + base + kt + qq * 4;
            CP_ASYNC16(smb + OFF_DJ + s * SZ_DJ + which * 512 + qq * 16, src);
        }
        CP_COMMIT();
    };

    auto buildP = [&](int s, int kt) {
        float* djd  = (float*)(sm + OFF_DJ + s * SZ_DJ);
        float* dje1 = djd + BK;
        float* dje2 = djd + 2 * BK;
        u16* Ps = (u16*)(sm + OFF_P + s * SZ_P) + rr * PST;
        unsigned w = g_adjbits[adjrow_base + (kt >> 5)];
#pragma unroll
        for (int c = 0; c < 16; c++) {
            int k0 = kb + 2 * c;
            int shb = 2 * c;
            float2 dd = *(float2*)&djd[k0];
            float2 e1 = *(float2*)&dje1[k0];
            float2 e2 = *(float2*)&dje2[k0];
            float x0 = srcv + dd.x;
            float p0 = (x0 > 0.f) ? E1s * e1.x : E2s * e2.x;
            if (!((w >> shb) & 1u)) p0 = 0.f;
            float x1 = srcv + dd.y;
            float p1 = (x1 > 0.f) ? E1s * e1.y : E2s * e2.y;
            if (!((w >> (shb + 1)) & 1u)) p1 = 0.f;
            __half2 hp = __floats2half2_rn(p0, p1);
            float2 rb = __half22float2(hp);   // rounded: num/den consistent
            psum += rb.x + rb.y;
            *(u32*)&Ps[k0] = *(u32*)&hp;
        }
    };

    auto do_mma = [&](int s) {
        u32 aP = smb + OFF_P + s * SZ_P + aoff;
        u32 bB = smb + OFF_B + s * SZ_B;
        int rL = lane & 15, cH = lane >> 4;
#pragma unroll
        for (int ks = 0; ks < 8; ks++) {
            u32 ap[2][4];
#pragma unroll
            for (int mt = 0; mt < 2; mt++) {
                u32 off = (u32)((mt * 16 * PST + ks * 16) * 2);
                ldsm4(ap[mt], aP + off);
            }
            int row = ks * 16 + rL;
            int rx = row & 7;
            u32 rowoff = (u32)(row * F * 2);
            u32 bh[NG][4];
#pragma unroll
            for (int ng = 0; ng < NG; ng++) {
                int c = (nb0 >> 3) + ng * 2 + cH;
                u32 addr = bB + rowoff + (u32)((c ^ rx) << 4);
                ldsm4t(bh[ng], addr);
            }
#pragma unroll
            for (int ng = 0; ng < NG; ng++)
#pragma unroll
                for (int mt = 0; mt < 2; mt++) {
                    mma_f16(acc[mt][2 * ng],     ap[mt], bh[ng]);
                    mma_f16(acc[mt][2 * ng + 1], ap[mt], bh[ng] + 2);
                }
        }
    };

    // ---- prologue ----
    if (tid == 0) {
        MBAR_INIT(smb + OFF_MB, 1);
        MBAR_INIT(smb + OFF_MB + 8, 1);
    }
    __syncthreads();
    stage(0, 0);
    mbar_wait(smb + OFF_MB, 0);
    CP_WAIT0();
    __syncthreads();
    buildP(0, 0);
    __syncthreads();

    // ---- mainloop ----
    for (int it = 0; it < NIT; ++it) {
        int s = it & 1;
        if (it + 1 < NIT) stage((it + 1) & 1, (it + 1) * BK);
        do_mma(s);
        if (it + 1 < NIT) {
            mbar_wait(smb + OFF_MB + 8 * ((it + 1) & 1), ((it + 1) >> 1) & 1);
            CP_WAIT0();
            buildP((it + 1) & 1, (it + 1) * BK);
        }
        __syncthreads();
    }

    {
        float tot = psum + __shfl_xor_sync(0xffffffffu, psum, 1);
        tot += __shfl_xor_sync(0xffffffffu, tot, 2);
        if (q == 0) rsum[rr] = tot;
    }
    __syncthreads();

    constexpr int CAT = HEADS * F;
    int r0 = mrow0 + (lane >> 2);
    int c0 = nb0 + (lane & 3) * 2;
#pragma unroll
    for (int mt = 0; mt < 2; mt++) {
        int ra = r0 + mt * 16, rb = ra + 8;
        float inva = 1.f / rsum[ra];
        float invb = 1.f / rsum[rb];
        float* outa = &hcat[(size_t)(m0 + ra) * CAT + h * F];
        float* outb = &hcat[(size_t)(m0 + rb) * CAT + h * F];
#pragma unroll
        for (int nt = 0; nt < NT; nt++) {
            int cc = c0 + nt * 8;
            float v0 = acc[mt][nt][0] * inva; v0 = v0 > 0.f ? v0 : expm1f(v0);
            float v1 = acc[mt][nt][1] * inva; v1 = v1 > 0.f ? v1 : expm1f(v1);
            float v2 = acc[mt][nt][2] * invb; v2 = v2 > 0.f ? v2 : expm1f(v2);
            float v3 = acc[mt][nt][3] * invb; v3 = v3 > 0.f ? v3 : expm1f(v3);
            *(float2*)&outa[cc] = make_float2(v0, v1);
            *(float2*)&outb[cc] = make_float2(v2, v3);
        }
    }
}

// ---------------- combine: out = relu( elu(A@LIN) + B@RES )  (+ maxenc zero) ----------------
__global__ __launch_bounds__(256) void combine_k(
    const float* __restrict__ A, int KA, const float* __restrict__ LIN,
    const float* __restrict__ B, int KB, const float* __restrict__ RES,
    float* __restrict__ out, int FOUT)
{
    if (blockIdx.x == 0 && blockIdx.y == 0 && threadIdx.x < HEADS)
        g_maxenc[threadIdx.x] = 0u;
    int m0 = blockIdx.x * 64, n0 = blockIdx.y * 64;
    __shared__ float Xs[64][17];
    __shared__ __align__(16) float Ws[16][64];
    int tid = threadIdx.x, ty = tid / 16, tx = tid % 16;
    float acc[4][4] = {};
    for (int kt = 0; kt < KA; kt += 16) {
        int r = tid >> 2, c = (tid & 3) * 4;
        float4 xv = *(const float4*)&A[(size_t)(m0 + r) * KA + kt + c];
        Xs[r][c] = xv.x; Xs[r][c + 1] = xv.y; Xs[r][c + 2] = xv.z; Xs[r][c + 3] = xv.w;
        int r2 = tid >> 4, c2 = (tid & 15) * 4;
        *(float4*)&Ws[r2][c2] = *(const float4*)&LIN[(size_t)(kt + r2) * FOUT + n0 + c2];
        __syncthreads();
#pragma unroll
        for (int k = 0; k < 16; k++) {
            float a[4], b[4];
#pragma unroll
            for (int i = 0; i < 4; i++) a[i] = Xs[ty * 4 + i][k];
#pragma unroll
            for (int j = 0; j < 4; j++) b[j] = Ws[k][tx * 4 + j];
#pragma unroll
            for (int i = 0; i < 4; i++)
#pragma unroll
                for (int j = 0; j < 4; j++) acc[i][j] = fmaf(a[i], b[j], acc[i][j]);
        }
        __syncthreads();
    }
#pragma unroll
    for (int i = 0; i < 4; i++)
#pragma unroll
        for (int j = 0; j < 4; j++)
            acc[i][j] = acc[i][j] > 0.f ? acc[i][j] : expm1f(acc[i][j]);
    for (int kt = 0; kt < KB; kt += 16) {
        int r = tid >> 2, c = (tid & 3) * 4;
        float4 xv = *(const float4*)&B[(size_t)(m0 + r) * KB + kt + c];
        Xs[r][c] = xv.x; Xs[r][c + 1] = xv.y; Xs[r][c + 2] = xv.z; Xs[r][c + 3] = xv.w;
        int r2 = tid >> 4, c2 = (tid & 15) * 4;
        *(float4*)&Ws[r2][c2] = *(const float4*)&RES[(size_t)(kt + r2) * FOUT + n0 + c2];
        __syncthreads();
#pragma unroll
        for (int k = 0; k < 16; k++) {
            float a[4], b[4];
#pragma unroll
            for (int i = 0; i < 4; i++) a[i] = Xs[ty * 4 + i][k];
#pragma unroll
            for (int j = 0; j < 4; j++) b[j] = Ws[k][tx * 4 + j];
#pragma unroll
            for (int i = 0; i < 4; i++)
#pragma unroll
                for (int j = 0; j < 4; j++) acc[i][j] = fmaf(a[i], b[j], acc[i][j]);
        }
        __syncthreads();
    }
#pragma unroll
    for (int i = 0; i < 4; i++) {
        float4 v;
        v.x = fmaxf(acc[i][0], 0.f); v.y = fmaxf(acc[i][1], 0.f);
        v.z = fmaxf(acc[i][2], 0.f); v.w = fmaxf(acc[i][3], 0.f);
        *(float4*)&out[(size_t)(m0 + ty * 4 + i) * FOUT + n0 + tx * 4] = v;
    }
}

// ---------------- host launcher ----------------
extern "C" void kernel_launch(void* const* d_in, const int* in_sizes, int n_in,
                              void* d_out, int out_size)
{
    const float* x    = (const float*)d_in[0];
    const int*   adj  = (const int*)d_in[1];
    const float* W1   = (const float*)d_in[2];
    const float* a1s  = (const float*)d_in[3];
    const float* a1d  = (const float*)d_in[4];
    const float* lin1 = (const float*)d_in[5];
    const float* res1 = (const float*)d_in[6];
    const float* W2   = (const float*)d_in[7];
    const float* a2s  = (const float*)d_in[8];
    const float* a2d  = (const float*)d_in[9];
    const float* lin2 = (const float*)d_in[10];
    const float* res2 = (const float*)d_in[11];
    float* out = (float*)d_out;

    float *whbuf, *hcat, *h1;
    u16 *whh;
    cudaGetSymbolAddress((void**)&whbuf, g_Whbuf);
    cudaGetSymbolAddress((void**)&hcat,  g_hcat);
    cudaGetSymbolAddress((void**)&h1,    g_h1);
    cudaGetSymbolAddress((void**)&whh,   g_WhH);

    constexpr int SZP = 64 * 136 * 2;                         // 17,408
    constexpr int SM1 = 2 * SZP + 2 * (128 * 128 * 2) + 2 * 1536 + 256 + 16; // 103,696
    constexpr int SM2 = 2 * SZP + 2 * (128 * 64 * 2)  + 2 * 1536 + 256 + 16; //  70,928
    cudaFuncSetAttribute(attn_mma_k<H1>, cudaFuncAttributeMaxDynamicSharedMemorySize, SM1);
    cudaFuncSetAttribute(attn_mma_k<H2>, cudaFuncAttributeMaxDynamicSharedMemorySize, SM2);

    pack_adj_k<<<NN * NN / 256, 256>>>(adj);

    // ---- layer 1 ----
    gemm_heads_k<<<dim3(NN / 64, H1 / 64, HEADS), 256>>>(x, W1, whbuf, whh, IN_DIM, H1);
    srcdst_k<<<HEADS * NN * 32 / 256, 256>>>(whbuf, a1s, a1d, H1);
    exps_k<<<(HEADS * NN + 255) / 256, 256>>>();
    attn_mma_k<H1><<<dim3(NN / 64, HEADS), 256, SM1>>>(whh, hcat);
    combine_k<<<dim3(NN / 64, H1 / 64), 256>>>(hcat, HEADS * H1, lin1, x, IN_DIM, res1, h1, H1);

    // ---- layer 2 ----
    gemm_heads_k<<<dim3(NN / 64, H2 / 64, HEADS), 256>>>(h1, W2, whbuf, whh, H1, H2);
    srcdst_k<<<HEADS * NN * 32 / 256, 256>>>(whbuf, a2s, a2d, H2);
    exps_k<<<(HEADS * NN + 255) / 256, 256>>>();
    attn_mma_k<H2><<<dim3(NN / 64, HEADS), 256, SM2>>>(whh, hcat);
    combine_k<<<dim3(NN / 64, H2 / 64), 256>>>(hcat, HEADS * H2, lin2, h1, H1, res2, out, H2);
}

// round 17
// speedup vs baseline: 1.3609x; 1.3609x over previous
#include <cuda_runtime.h>
#include <cuda_fp16.h>
#include <math.h>
#include <cstdint>

#define NN 3072
#define HEADS 4
#define IN_DIM 256
#define H1 128
#define H2 64
#define ADJW (NN/32)

typedef unsigned int u32;
typedef unsigned short u16;

// ---------------- scratch ----------------
__device__ __align__(16) unsigned g_adjbits[NN * ADJW];
__device__ __align__(16) float g_src[HEADS * NN];
__device__ __align__(16) float g_dst[HEADS * NN];
__device__ __align__(16) float g_e1s[HEADS * NN];
__device__ __align__(16) float g_e2s[HEADS * NN];
__device__ __align__(16) float g_e1d[HEADS * NN];
__device__ __align__(16) float g_e2d[HEADS * NN];
__device__ __align__(16) u16 g_WhH[HEADS * NN * H1];   // fp16 Wh, 128-row-tile-major + swizzled
__device__ __align__(16) float g_hcat[NN * HEADS * H1];
__device__ __align__(16) float g_h1[NN * H1];

// ---------------- helpers ----------------
__device__ __forceinline__ u32 smem_u32(const void* p) {
    u32 a;
    asm("{ .reg .u64 t; cvta.to.shared.u64 t, %1; cvt.u32.u64 %0, t; }" : "=r"(a) : "l"(p));
    return a;
}
__device__ __forceinline__ void ldsm4(u32* r, u32 addr) {
    asm volatile("ldmatrix.sync.aligned.m8n8.x4.shared.b16 {%0,%1,%2,%3}, [%4];"
                 : "=r"(r[0]), "=r"(r[1]), "=r"(r[2]), "=r"(r[3]) : "r"(addr));
}
__device__ __forceinline__ void ldsm4t(u32* r, u32 addr) {
    asm volatile("ldmatrix.sync.aligned.m8n8.x4.trans.shared.b16 {%0,%1,%2,%3}, [%4];"
                 : "=r"(r[0]), "=r"(r[1]), "=r"(r[2]), "=r"(r[3]) : "r"(addr));
}
__device__ __forceinline__ void mma_f16(float* d, const u32* a, const u32* b) {
    asm volatile(
        "mma.sync.aligned.m16n8k16.row.col.f32.f16.f16.f32 "
        "{%0,%1,%2,%3}, {%4,%5,%6,%7}, {%8,%9}, {%0,%1,%2,%3};"
        : "+f"(d[0]), "+f"(d[1]), "+f"(d[2]), "+f"(d[3])
        : "r"(a[0]), "r"(a[1]), "r"(a[2]), "r"(a[3]), "r"(b[0]), "r"(b[1]));
}
#define CP_ASYNC16(dst, src) asm volatile("cp.async.cg.shared.global [%0], [%1], 16;" :: "r"(dst), "l"(src))
#define CP_COMMIT()  asm volatile("cp.async.commit_group;" ::: "memory")
#define CP_WAIT0()   asm volatile("cp.async.wait_group 0;" ::: "memory")
#define MBAR_INIT(a, c) asm volatile("mbarrier.init.shared.b64 [%0], %1;" :: "r"(a), "r"(c) : "memory")
#define MBAR_EXPECT_TX(a, bytes) \
    asm volatile("mbarrier.arrive.expect_tx.shared.b64 _, [%0], %1;" :: "r"(a), "r"(bytes) : "memory")
__device__ __forceinline__ void mbar_wait(u32 mbar, u32 parity) {
    asm volatile(
        "{\n\t.reg .pred P1;\n\t"
        "WL%=:\n\t"
        "mbarrier.try_wait.parity.acquire.cta.shared::cta.b64 P1, [%0], %1, 0x989680;\n\t"
        "@P1 bra.uni WD%=;\n\t"
        "bra.uni WL%=;\n\t"
        "WD%=:\n\t}"
        :: "r"(mbar), "r"(parity) : "memory");
}
#define CP_BULK(dst, src, bytes, mbar) \
    asm volatile("cp.async.bulk.shared::cta.global.mbarrier::complete_tx::bytes [%0], [%1], %2, [%3];" \
                 :: "r"(dst), "l"(src), "r"(bytes), "r"(mbar) : "memory")

// ---------------- adjacency bit-pack (+ zero src/dst for layer 1) ----------------
__global__ void pack_adj_k(const int* __restrict__ adj) {
    int idx = blockIdx.x * blockDim.x + threadIdx.x;
    if (idx < HEADS * NN) { g_src[idx] = 0.f; g_dst[idx] = 0.f; }
    int v = adj[idx] > 0;
    unsigned m = __ballot_sync(0xffffffffu, v);
    if ((idx & 31) == 0) g_adjbits[idx >> 5] = m;
}

// ---------------- per-head GEMM: fp16 tiled Wh + fused src/dst partial dots ----------------
__global__ __launch_bounds__(256) void gemm_heads_k(
    const float* __restrict__ X, const float* __restrict__ W,
    const float* __restrict__ as, const float* __restrict__ ad,
    u16* __restrict__ hi, int K, int F)
{
    int h = blockIdx.z;
    int m0 = blockIdx.x * 64, n0 = blockIdx.y * 64;
    const float* Wp = W + (size_t)h * K * F;
    char* hibase = (char*)hi + (size_t)h * NN * F * 2;
    __shared__ float Xs[64][17];
    __shared__ __align__(16) float Ws[16][64];
    int tid = threadIdx.x, ty = tid / 16, tx = tid % 16;
    float acc[4][4] = {};
    for (int kt = 0; kt < K; kt += 16) {
        int r = tid >> 2, c = (tid & 3) * 4;
        float4 xv = *(const float4*)&X[(size_t)(m0 + r) * K + kt + c];
        Xs[r][c] = xv.x; Xs[r][c + 1] = xv.y; Xs[r][c + 2] = xv.z; Xs[r][c + 3] = xv.w;
        int r2 = tid >> 4, c2 = (tid & 15) * 4;
        *(float4*)&Ws[r2][c2] = *(const float4*)&Wp[(size_t)(kt + r2) * F + n0 + c2];
        __syncthreads();
#pragma unroll
        for (int k = 0; k < 16; k++) {
            float a[4], b[4];
#pragma unroll
            for (int i = 0; i < 4; i++) a[i] = Xs[ty * 4 + i][k];
#pragma unroll
            for (int j = 0; j < 4; j++) b[j] = Ws[k][tx * 4 + j];
#pragma unroll
            for (int i = 0; i < 4; i++)
#pragma unroll
                for (int j = 0; j < 4; j++) acc[i][j] = fmaf(a[i], b[j], acc[i][j]);
        }
        __syncthreads();
    }
    int f0 = n0 + tx * 4;
    // fp16 tile-major store
#pragma unroll
    for (int i = 0; i < 4; i++) {
        int n = m0 + ty * 4 + i;
        __half2 h01 = __floats2half2_rn(acc[i][0], acc[i][1]);
        __half2 h23 = __floats2half2_rn(acc[i][2], acc[i][3]);
        uint2 pk;
        pk.x = *(u32*)&h01;
        pk.y = *(u32*)&h23;
        int t = n >> 7, r = n & 127;
        int c = f0 >> 3;
        size_t off = (size_t)t * (128 * F * 2) + (size_t)r * F * 2
                   + (size_t)((c ^ (r & 7)) << 4) + (f0 & 7) * 2;
        *(uint2*)(hibase + off) = pk;
    }
    // fused src/dst partial dot products
    float as4[4], ad4[4];
#pragma unroll
    for (int j = 0; j < 4; j++) { as4[j] = as[h * F + f0 + j]; ad4[j] = ad[h * F + f0 + j]; }
#pragma unroll
    for (int i = 0; i < 4; i++) {
        float ps = 0.f, pd = 0.f;
#pragma unroll
        for (int j = 0; j < 4; j++) {
            ps = fmaf(acc[i][j], as4[j], ps);
            pd = fmaf(acc[i][j], ad4[j], pd);
        }
#pragma unroll
        for (int o = 8; o; o >>= 1) {
            ps += __shfl_xor_sync(0xffffffffu, ps, o, 16);
            pd += __shfl_xor_sync(0xffffffffu, pd, o, 16);
        }
        if (tx == 0) {
            int n = m0 + ty * 4 + i;
            atomicAdd(&g_src[h * NN + n], ps);
            atomicAdd(&g_dst[h * NN + n], pd);
        }
    }
}

// ---------------- per-head max(dst) + factored exps (one block per head) ----------------
__global__ __launch_bounds__(256) void maxexps_k() {
    int h = blockIdx.x;
    int tid = threadIdx.x;
    __shared__ float smax[256];
    float m = -1e30f;
    for (int i = tid; i < NN; i += 256) m = fmaxf(m, g_dst[h * NN + i]);
    smax[tid] = m; __syncthreads();
    for (int s = 128; s; s >>= 1) {
        if (tid < s) smax[tid] = fmaxf(smax[tid], smax[tid + s]);
        __syncthreads();
    }
    float mx = smax[0];
    for (int i = tid; i < NN; i += 256) {
        int idx = h * NN + i;
        float s = g_src[idx], d = g_dst[idx];
        float x = s + mx;
        float c = x > 0.f ? x : 0.2f * x;
        g_e1s[idx] = expf(s - c);
        g_e2s[idx] = expf(0.2f * s - c);
        g_e1d[idx] = expf(d);
        g_e2d[idx] = expf(0.2f * d);
    }
}

// ---------------- HMMA attention: D = P @ Wh (fp16, BM=128, BK=128) ----------------
// grid (NN/128, HEADS), block 256 (8 warps: 4 m-groups x 2 n-groups)
template <int F>
__global__ __launch_bounds__(256) void attn_mma_k(
    const u16* __restrict__ WhH, float* __restrict__ hcat)
{
    constexpr int BK = 128;
    constexpr int NIT = NN / BK;          // 24
    constexpr int PST = BK + 8;           // 136 halves
    constexpr int NW = F / 2;
    constexpr int NT = NW / 8;            // 8 (F=128) / 4 (F=64)
    constexpr int NG = NT / 2;
    constexpr int SZ_P = 128 * PST * 2;   // 34,816 B
    constexpr int SZ_B = BK * F * 2;
    constexpr int SZ_DJ = 3 * BK * 4;     // 1,536 B
    constexpr int OFF_P = 0;
    constexpr int OFF_B = 2 * SZ_P;
    constexpr int OFF_DJ = OFF_B + 2 * SZ_B;
    constexpr int OFF_RS = OFF_DJ + 2 * SZ_DJ;
    constexpr int OFF_MB = OFF_RS + 512;

    extern __shared__ char sm[];
    u32 smb = smem_u32(sm);
    float* rsum = (float*)(sm + OFF_RS);

    int tid = threadIdx.x, wid = tid >> 5, lane = tid & 31;
    int h = blockIdx.y, m0 = blockIdx.x * 128;
    int base = h * NN;
    const char* WHt = (const char*)WhH + (size_t)base * F * 2;

    int rr = tid >> 1, half = tid & 1, kb = half * 64;
    float E1s = g_e1s[base + m0 + rr];
    float E2s = g_e2s[base + m0 + rr];
    float srcv = g_src[base + m0 + rr];
    float psum = 0.f;
    u32 adjrow_base = (u32)((m0 + rr) * ADJW) + half * 2;

    int wm = wid & 3, wn = wid >> 2;
    int mrow0 = wm * 32, nb0 = wn * NW;
    float acc[2][NT][4];
#pragma unroll
    for (int i = 0; i < 2; i++)
#pragma unroll
        for (int j = 0; j < NT; j++)
#pragma unroll
            for (int q = 0; q < 4; q++) acc[i][j][q] = 0.f;

    u32 aoff = (u32)(((mrow0 + (lane & 15)) * PST + (lane >> 4) * 8) * 2);

    auto stage = [&](int s, int kt) {
        if (tid == 0) {
            u32 mb = smb + OFF_MB + s * 8;
            MBAR_EXPECT_TX(mb, (u32)SZ_B);
            CP_BULK(smb + OFF_B + s * SZ_B, WHt + (size_t)(kt / BK) * SZ_B, (u32)SZ_B, mb);
        }
        if (tid < 96) {
            int which = tid >> 5, qq = tid & 31;
            const float* src = (which == 0 ? g_dst : which == 1 ? g_e1d : g_e2d)
                               + base + kt + qq * 4;
            CP_ASYNC16(smb + OFF_DJ + s * SZ_DJ + which * 512 + qq * 16, src);
        }
        CP_COMMIT();
    };

    auto buildP = [&](int s, int kt) {
        float* djd  = (float*)(sm + OFF_DJ + s * SZ_DJ);
        float* dje1 = djd + BK;
        float* dje2 = djd + 2 * BK;
        u16* Ps = (u16*)(sm + OFF_P + s * SZ_P) + rr * PST;
        unsigned w0 = g_adjbits[adjrow_base + (kt >> 5)];
        unsigned w1 = g_adjbits[adjrow_base + (kt >> 5) + 1];
#pragma unroll
        for (int c = 0; c < 32; c++) {
            int k0 = kb + 2 * c;
            unsigned w = (c < 16) ? w0 : w1;
            int shb = (2 * c) & 31;
            float2 dd = *(float2*)&djd[k0];
            float2 e1 = *(float2*)&dje1[k0];
            float2 e2 = *(float2*)&dje2[k0];
            float x0 = srcv + dd.x;
            float p0 = (x0 > 0.f) ? E1s * e1.x : E2s * e2.x;
            if (!((w >> shb) & 1u)) p0 = 0.f;
            float x1 = srcv + dd.y;
            float p1 = (x1 > 0.f) ? E1s * e1.y : E2s * e2.y;
            if (!((w >> (shb + 1)) & 1u)) p1 = 0.f;
            __half2 hp = __floats2half2_rn(p0, p1);
            float2 rb = __half22float2(hp);   // rounded: num/den consistent
            psum += rb.x + rb.y;
            *(u32*)&Ps[k0] = *(u32*)&hp;
        }
    };

    auto do_mma = [&](int s) {
        u32 aP = smb + OFF_P + s * SZ_P + aoff;
        u32 bB = smb + OFF_B + s * SZ_B;
        int rL = lane & 15, cH = lane >> 4;
#pragma unroll
        for (int ks = 0; ks < 8; ks++) {
            u32 ap[2][4];
#pragma unroll
            for (int mt = 0; mt < 2; mt++) {
                u32 off = (u32)((mt * 16 * PST + ks * 16) * 2);
                ldsm4(ap[mt], aP + off);
            }
            int row = ks * 16 + rL;
            int rx = row & 7;
            u32 rowoff = (u32)(row * F * 2);
            u32 bh[NG][4];
#pragma unroll
            for (int ng = 0; ng < NG; ng++) {
                int c = (nb0 >> 3) + ng * 2 + cH;
                u32 addr = bB + rowoff + (u32)((c ^ rx) << 4);
                ldsm4t(bh[ng], addr);
            }
#pragma unroll
            for (int ng = 0; ng < NG; ng++)
#pragma unroll
                for (int mt = 0; mt < 2; mt++) {
                    mma_f16(acc[mt][2 * ng],     ap[mt], bh[ng]);
                    mma_f16(acc[mt][2 * ng + 1], ap[mt], bh[ng] + 2);
                }
        }
    };

    // ---- prologue ----
    if (tid == 0) {
        MBAR_INIT(smb + OFF_MB, 1);
        MBAR_INIT(smb + OFF_MB + 8, 1);
    }
    __syncthreads();
    stage(0, 0);
    mbar_wait(smb + OFF_MB, 0);
    CP_WAIT0();
    __syncthreads();
    buildP(0, 0);
    __syncthreads();

    // ---- mainloop ----
    for (int it = 0; it < NIT; ++it) {
        int s = it & 1;
        if (it + 1 < NIT) stage((it + 1) & 1, (it + 1) * BK);
        do_mma(s);
        if (it + 1 < NIT) {
            mbar_wait(smb + OFF_MB + 8 * ((it + 1) & 1), ((it + 1) >> 1) & 1);
            CP_WAIT0();
            buildP((it + 1) & 1, (it + 1) * BK);
        }
        __syncthreads();
    }

    {
        float tot = psum + __shfl_xor_sync(0xffffffffu, psum, 1);
        if (!half) rsum[rr] = tot;
    }
    __syncthreads();

    constexpr int CAT = HEADS * F;
    int r0 = mrow0 + (lane >> 2);
    int c0 = nb0 + (lane & 3) * 2;
#pragma unroll
    for (int mt = 0; mt < 2; mt++) {
        int ra = r0 + mt * 16, rb = ra + 8;
        float inva = 1.f / rsum[ra];
        float invb = 1.f / rsum[rb];
        float* outa = &hcat[(size_t)(m0 + ra) * CAT + h * F];
        float* outb = &hcat[(size_t)(m0 + rb) * CAT + h * F];
#pragma unroll
        for (int nt = 0; nt < NT; nt++) {
            int cc = c0 + nt * 8;
            float v0 = acc[mt][nt][0] * inva; v0 = v0 > 0.f ? v0 : expm1f(v0);
            float v1 = acc[mt][nt][1] * inva; v1 = v1 > 0.f ? v1 : expm1f(v1);
            float v2 = acc[mt][nt][2] * invb; v2 = v2 > 0.f ? v2 : expm1f(v2);
            float v3 = acc[mt][nt][3] * invb; v3 = v3 > 0.f ? v3 : expm1f(v3);
            *(float2*)&outa[cc] = make_float2(v0, v1);
            *(float2*)&outb[cc] = make_float2(v2, v3);
        }
    }
}

// ---------------- combine: out = relu( elu(A@LIN) + B@RES )  (+ zero src/dst) ----------------
__global__ __launch_bounds__(256) void combine_k(
    const float* __restrict__ A, int KA, const float* __restrict__ LIN,
    const float* __restrict__ B, int KB, const float* __restrict__ RES,
    float* __restrict__ out, int FOUT)
{
    {
        int gi = (blockIdx.y * gridDim.x + blockIdx.x) * blockDim.x + threadIdx.x;
        if (gi < HEADS * NN) { g_src[gi] = 0.f; g_dst[gi] = 0.f; }
    }
    int m0 = blockIdx.x * 64, n0 = blockIdx.y * 64;
    __shared__ float Xs[64][17];
    __shared__ __align__(16) float Ws[16][64];
    int tid = threadIdx.x, ty = tid / 16, tx = tid % 16;
    float acc[4][4] = {};
    for (int kt = 0; kt < KA; kt += 16) {
        int r = tid >> 2, c = (tid & 3) * 4;
        float4 xv = *(const float4*)&A[(size_t)(m0 + r) * KA + kt + c];
        Xs[r][c] = xv.x; Xs[r][c + 1] = xv.y; Xs[r][c + 2] = xv.z; Xs[r][c + 3] = xv.w;
        int r2 = tid >> 4, c2 = (tid & 15) * 4;
        *(float4*)&Ws[r2][c2] = *(const float4*)&LIN[(size_t)(kt + r2) * FOUT + n0 + c2];
        __syncthreads();
#pragma unroll
        for (int k = 0; k < 16; k++) {
            float a[4], b[4];
#pragma unroll
            for (int i = 0; i < 4; i++) a[i] = Xs[ty * 4 + i][k];
#pragma unroll
            for (int j = 0; j < 4; j++) b[j] = Ws[k][tx * 4 + j];
#pragma unroll
            for (int i = 0; i < 4; i++)
#pragma unroll
                for (int j = 0; j < 4; j++) acc[i][j] = fmaf(a[i], b[j], acc[i][j]);
        }
        __syncthreads();
    }
#pragma unroll
    for (int i = 0; i < 4; i++)
#pragma unroll
        for (int j = 0; j < 4; j++)
            acc[i][j] = acc[i][j] > 0.f ? acc[i][j] : expm1f(acc[i][j]);
    for (int kt = 0; kt < KB; kt += 16) {
        int r = tid >> 2, c = (tid & 3) * 4;
        float4 xv = *(const float4*)&B[(size_t)(m0 + r) * KB + kt + c];
        Xs[r][c] = xv.x; Xs[r][c + 1] = xv.y; Xs[r][c + 2] = xv.z; Xs[r][c + 3] = xv.w;
        int r2 = tid >> 4, c2 = (tid & 15) * 4;
        *(float4*)&Ws[r2][c2] = *(const float4*)&RES[(size_t)(kt + r2) * FOUT + n0 + c2];
        __syncthreads();
#pragma unroll
        for (int k = 0; k < 16; k++) {
            float a[4], b[4];
#pragma unroll
            for (int i = 0; i < 4; i++) a[i] = Xs[ty * 4 + i][k];
#pragma unroll
            for (int j = 0; j < 4; j++) b[j] = Ws[k][tx * 4 + j];
#pragma unroll
            for (int i = 0; i < 4; i++)
#pragma unroll
                for (int j = 0; j < 4; j++) acc[i][j] = fmaf(a[i], b[j], acc[i][j]);
        }
        __syncthreads();
    }
#pragma unroll
    for (int i = 0; i < 4; i++) {
        float4 v;
        v.x = fmaxf(acc[i][0], 0.f); v.y = fmaxf(acc[i][1], 0.f);
        v.z = fmaxf(acc[i][2], 0.f); v.w = fmaxf(acc[i][3], 0.f);
        *(float4*)&out[(size_t)(m0 + ty * 4 + i) * FOUT + n0 + tx * 4] = v;
    }
}

// ---------------- host launcher ----------------
extern "C" void kernel_launch(void* const* d_in, const int* in_sizes, int n_in,
                              void* d_out, int out_size)
{
    const float* x    = (const float*)d_in[0];
    const int*   adj  = (const int*)d_in[1];
    const float* W1   = (const float*)d_in[2];
    const float* a1s  = (const float*)d_in[3];
    const float* a1d  = (const float*)d_in[4];
    const float* lin1 = (const float*)d_in[5];
    const float* res1 = (const float*)d_in[6];
    const float* W2   = (const float*)d_in[7];
    const float* a2s  = (const float*)d_in[8];
    const float* a2d  = (const float*)d_in[9];
    const float* lin2 = (const float*)d_in[10];
    const float* res2 = (const float*)d_in[11];
    float* out = (float*)d_out;

    float *hcat, *h1;
    u16 *whh;
    cudaGetSymbolAddress((void**)&hcat, g_hcat);
    cudaGetSymbolAddress((void**)&h1,   g_h1);
    cudaGetSymbolAddress((void**)&whh,  g_WhH);

    constexpr int SZP = 128 * 136 * 2;                       // 34,816
    constexpr int SM1 = 2 * SZP + 2 * (128 * 128 * 2) + 2 * 1536 + 512 + 16; // 138,768
    constexpr int SM2 = 2 * SZP + 2 * (128 * 64 * 2)  + 2 * 1536 + 512 + 16; // 106,000
    cudaFuncSetAttribute(attn_mma_k<H1>, cudaFuncAttributeMaxDynamicSharedMemorySize, SM1);
    cudaFuncSetAttribute(attn_mma_k<H2>, cudaFuncAttributeMaxDynamicSharedMemorySize, SM2);

    // pack adjacency + zero src/dst for layer 1
    pack_adj_k<<<NN * NN / 256, 256>>>(adj);

    // ---- layer 1 ----
    gemm_heads_k<<<dim3(NN / 64, H1 / 64, HEADS), 256>>>(x, W1, a1s, a1d, whh, IN_DIM, H1);
    maxexps_k<<<HEADS, 256>>>();
    attn_mma_k<H1><<<dim3(NN / 128, HEADS), 256, SM1>>>(whh, hcat);
    combine_k<<<dim3(NN / 64, H1 / 64), 256>>>(hcat, HEADS * H1, lin1, x, IN_DIM, res1, h1, H1); // zeroes src/dst

    // ---- layer 2 ----
    gemm_heads_k<<<dim3(NN / 64, H2 / 64, HEADS), 256>>>(h1, W2, a2s, a2d, whh, H1, H2);
    maxexps_k<<<HEADS, 256>>>();
    attn_mma_k<H2><<<dim3(NN / 128, HEADS), 256, SM2>>>(whh, hcat);
    combine_k<<<dim3(NN / 64, H2 / 64), 256>>>(hcat, HEADS * H2, lin2, h1, H1, res2, out, H2);
}